// round 1
// baseline (speedup 1.0000x reference)
#include <cuda_runtime.h>

// Problem constants (fixed shapes per reference)
#define Tt 2000
#define Bb 64
#define Vv 163
#define Lmax 200
#define Ss 401            // 2*Lmax + 1
#define NEGV (-1e30f)
#define LOG2E 1.4426950408889634f
#define LN2 0.6931471805599453f

// Scratch (static device globals; no allocation)
__device__ float g_lse2[Tt * Bb];   // log2-sum-exp2 per (t,b)
__device__ float g_losses[Bb];

__device__ __forceinline__ float ex2f_(float x) {
    float y; asm("ex2.approx.f32 %0, %1;" : "=f"(y) : "f"(x)); return y;
}
__device__ __forceinline__ float lg2f_(float x) {
    float y; asm("lg2.approx.f32 %0, %1;" : "=f"(y) : "f"(x)); return y;
}

// ---------------------------------------------------------------------------
// Kernel 1: per-(t,b) log2-sum-exp2 over vocab. One warp per row.
// ---------------------------------------------------------------------------
__global__ void lse_kernel(const float* __restrict__ logits) {
    int w = (blockIdx.x * blockDim.x + threadIdx.x) >> 5;
    int lane = threadIdx.x & 31;
    if (w >= Tt * Bb) return;
    const float* row = logits + (size_t)w * Vv;
    float y[6];
    float m = NEGV;
#pragma unroll
    for (int i = 0; i < 6; i++) {
        int v = lane + 32 * i;
        y[i] = (v < Vv) ? row[v] * LOG2E : NEGV;
        m = fmaxf(m, y[i]);
    }
#pragma unroll
    for (int o = 16; o > 0; o >>= 1) m = fmaxf(m, __shfl_xor_sync(0xffffffffu, m, o));
    float s = 0.f;
#pragma unroll
    for (int i = 0; i < 6; i++) s += ex2f_(y[i] - m);
#pragma unroll
    for (int o = 16; o > 0; o >>= 1) s += __shfl_xor_sync(0xffffffffu, s, o);
    if (lane == 0) g_lse2[w] = m + lg2f_(s);
}

// ---------------------------------------------------------------------------
// Kernel 2: CTC forward recursion. One CTA per utterance, one thread per
// extended-label state. Base-2 log domain. Row of log-probs for step t+1 is
// prefetched (regs -> smem, 2 steps ahead) while step t computes.
// One __syncthreads per time step (double-buffered alpha + row).
// ---------------------------------------------------------------------------
__global__ void __launch_bounds__(416, 1) ctc_alpha_kernel(
    const float* __restrict__ logits,
    const int*   __restrict__ labels,
    const int*   __restrict__ act_lens,
    const int*   __restrict__ label_lens)
{
    const int b   = blockIdx.x;
    const int tid = threadIdx.x;

    __shared__ float rowbuf[2][Vv];
    __shared__ float alpha[2][Ss + 2];   // [buf][0..1] = NEG pads, states at +2

    const int act_len   = act_lens[b];
    const int label_len = label_lens[b];

    const int  s      = tid;
    const bool active = (s < Ss);

    int  my_ext = 0;
    bool allow  = false;
    if (active && (s & 1)) {
        int li  = s >> 1;                 // (s-1)/2 for odd s
        int lab = labels[b * Lmax + li];
        my_ext  = lab;
        allow   = (s == 1) || (lab != labels[b * Lmax + li - 1]);
    }
    const bool valid = active && (s < 2 * label_len + 1);

    if (tid < 2) { alpha[0][tid] = NEGV; alpha[1][tid] = NEGV; }

    float pref = 0.f, pref_lse = 0.f;
    if (tid < Vv) {
        rowbuf[0][tid] = fmaf(logits[(size_t)b * Vv + tid], LOG2E, -g_lse2[b]);
    }
    __syncthreads();

    float a = (valid && s < 2) ? rowbuf[0][my_ext] : NEGV;
    if (active) alpha[0][2 + s] = a;

    if (tid < Vv) {
        int t1 = (Tt > 1) ? 1 : 0;
        rowbuf[1][tid] = fmaf(logits[((size_t)t1 * Bb + b) * Vv + tid], LOG2E,
                              -g_lse2[t1 * Bb + b]);
        int t2 = (2 < Tt) ? 2 : (Tt - 1);
        pref     = logits[((size_t)t2 * Bb + b) * Vv + tid];
        pref_lse = g_lse2[t2 * Bb + b];
    }

    for (int t = 1; t < act_len; ++t) {
        __syncthreads();
        if (active) {
            const float* rc = rowbuf[t & 1];
            const float* ap = alpha[(t + 1) & 1];
            float lp = rc[my_ext];
            float a1 = ap[2 + s - 1];
            float a2 = allow ? ap[2 + s - 2] : NEGV;
            float m  = fmaxf(a, fmaxf(a1, a2));
            float sum = ex2f_(a - m) + ex2f_(a1 - m) + ex2f_(a2 - m);
            float anew = m + lg2f_(sum) + lp;
            a = valid ? anew : NEGV;
            alpha[t & 1][2 + s] = a;
        }
        if (tid < Vv) {
            rowbuf[(t + 1) & 1][tid] = fmaf(pref, LOG2E, -pref_lse);
            int tn = t + 2; if (tn > Tt - 1) tn = Tt - 1;
            pref     = logits[((size_t)tn * Bb + b) * Vv + tid];
            pref_lse = g_lse2[tn * Bb + b];
        }
    }
    __syncthreads();

    if (tid == 0) {
        const float* A = alpha[(act_len - 1) & 1] + 2;
        int   end = 2 * label_len;
        float al  = A[end];
        float apv = (label_len > 0) ? A[end - 1] : NEGV;
        float m   = fmaxf(al, apv);
        float ll2 = m + lg2f_(ex2f_(al - m) + ex2f_(apv - m));
        g_losses[b] = -ll2 * LN2;   // back to natural log
    }
}

// ---------------------------------------------------------------------------
// Kernel 3: total = sum(losses) / sum(act_lens)
// ---------------------------------------------------------------------------
__global__ void reduce_kernel(const int* __restrict__ act_lens,
                              float* __restrict__ out)
{
    int lane = threadIdx.x;   // 32 threads, each handles lane and lane+32
    float l = g_losses[lane] + g_losses[lane + 32];
    float n = (float)act_lens[lane] + (float)act_lens[lane + 32];
#pragma unroll
    for (int o = 16; o > 0; o >>= 1) {
        l += __shfl_xor_sync(0xffffffffu, l, o);
        n += __shfl_xor_sync(0xffffffffu, n, o);
    }
    if (lane == 0) out[0] = l / n;
}

extern "C" void kernel_launch(void* const* d_in, const int* in_sizes, int n_in,
                              void* d_out, int out_size)
{
    const float* logits     = (const float*)d_in[0];
    const int*   labels     = (const int*)  d_in[1];
    const int*   act_lens   = (const int*)  d_in[2];
    const int*   label_lens = (const int*)  d_in[3];

    const int rows = Tt * Bb;                      // 128000 warps
    lse_kernel<<<(rows * 32 + 255) / 256, 256>>>(logits);
    ctc_alpha_kernel<<<Bb, 416>>>(logits, labels, act_lens, label_lens);
    reduce_kernel<<<1, 32>>>(act_lens, (float*)d_out);
}

// round 2
// speedup vs baseline: 1.3043x; 1.3043x over previous
#include <cuda_runtime.h>

// Fixed problem shapes
#define Tt 2000
#define Bb 64
#define Vv 163
#define Lmax 200
#define Ss 401              // 2*Lmax + 1
#define NW 13               // warps per CTA (416 threads)
#define NEGV (-1e30f)
#define LOG2E 1.4426950408889634f
#define LN2 0.6931471805599453f

// Static device scratch (no allocation allowed)
__device__ float g_lse2[Bb * Tt];   // transposed: [b][t], log2-sum-exp2 per frame
__device__ float g_llraw[Bb];       // raw (unnormalized) log2 forward prob
__device__ float g_losses[Bb];

__device__ __forceinline__ float ex2f_(float x) {
    float y; asm("ex2.approx.f32 %0, %1;" : "=f"(y) : "f"(x)); return y;
}
__device__ __forceinline__ float lg2f_(float x) {
    float y; asm("lg2.approx.f32 %0, %1;" : "=f"(y) : "f"(x)); return y;
}

// ---------------------------------------------------------------------------
// Kernel 1: per-(t,b) log2-sum-exp2 over vocab. One warp per row.
// Writes transposed [b][t] so the finalize kernel reads coalesced.
// ---------------------------------------------------------------------------
__global__ void lse_kernel(const float* __restrict__ logits) {
    int w = (blockIdx.x * blockDim.x + threadIdx.x) >> 5;
    int lane = threadIdx.x & 31;
    if (w >= Tt * Bb) return;
    const float* row = logits + (size_t)w * Vv;
    float y[6];
    float m = NEGV;
#pragma unroll
    for (int i = 0; i < 6; i++) {
        int v = lane + 32 * i;
        y[i] = (v < Vv) ? row[v] * LOG2E : NEGV;
        m = fmaxf(m, y[i]);
    }
#pragma unroll
    for (int o = 16; o > 0; o >>= 1) m = fmaxf(m, __shfl_xor_sync(0xffffffffu, m, o));
    float sv = 0.f;
#pragma unroll
    for (int i = 0; i < 6; i++) sv += ex2f_(y[i] - m);
#pragma unroll
    for (int o = 16; o > 0; o >>= 1) sv += __shfl_xor_sync(0xffffffffu, sv, o);
    if (lane == 0) {
        int t = w / Bb, b = w % Bb;
        g_lse2[b * Tt + t] = m + lg2f_(sv);
    }
}

// ---------------------------------------------------------------------------
// Kernel 2: CTC forward recursion on RAW log2-logits (shift-invariance:
// softmax normalization folded out; corrected in finalize).
// One CTA per utterance, one thread per state. Alpha lives in registers;
// neighbor values via warp shuffle; only 2 boundary floats/warp via SMEM.
// ---------------------------------------------------------------------------
__global__ void __launch_bounds__(416, 1) ctc_alpha_kernel(
    const float* __restrict__ logits,
    const int*   __restrict__ labels,
    const int*   __restrict__ act_lens,
    const int*   __restrict__ label_lens)
{
    const int b    = blockIdx.x;
    const int tid  = threadIdx.x;
    const int lane = tid & 31;
    const int w    = tid >> 5;

    __shared__ float bnd[2][NW][2];   // double-buffered warp-boundary alphas
    __shared__ float afin[Ss];

    const int act_len   = act_lens[b];
    const int label_len = label_lens[b];
    const int s = tid;

    int  my_ext = 0;
    bool allow  = false;
    if (s < Ss && (s & 1)) {
        int li  = s >> 1;
        int lab = labels[b * Lmax + li];
        my_ext  = lab;
        allow   = (s == 1) || (lab != labels[b * Lmax + li - 1]);
    }
    const bool valid = (s < Ss) && (s < 2 * label_len + 1);

    const size_t stride = (size_t)Bb * Vv;
    const float* gp = logits + (size_t)b * Vv + my_ext;   // t=0 element

    float a = (valid && s < 2) ? gp[0] * LOG2E : NEGV;
    if (lane >= 30) bnd[0][w][lane - 30] = a;

    // Prefetch pipeline: lpB = lp(t=1), lpC = lp(t=2)
    float lpB = gp[stride]     * LOG2E;
    float lpC = gp[2 * stride] * LOG2E;
    __syncthreads();

    for (int t = 1; t < act_len; ++t) {
        const int pb = (t - 1) & 1, cb = t & 1;
        float b0 = NEGV, b1 = NEGV;
        if (lane < 2 && w > 0) {
            b0 = bnd[pb][w - 1][0];
            b1 = bnd[pb][w - 1][1];
        }
        float a1 = __shfl_up_sync(0xffffffffu, a, 1);
        float a2 = __shfl_up_sync(0xffffffffu, a, 2);
        if (lane == 0)      { a1 = b1; a2 = b0; }
        else if (lane == 1) { a2 = b1; }
        if (!allow) a2 = NEGV;

        // logaddexp3 with the max contributing ex2(0)=1 (3 MUFU total)
        float M  = fmaxf(a, a1);
        float m1 = fminf(a, a1);
        float M2 = fmaxf(M, a2);
        float m2 = fminf(M, a2);
        float sum  = 1.0f + ex2f_(m1 - M2) + ex2f_(m2 - M2);
        float anew = M2 + lg2f_(sum) + lpB;
        a = valid ? anew : NEGV;

        if (lane >= 30) bnd[cb][w][lane - 30] = a;

        // rotate prefetch: load lp(t+2), consumed two iterations later
        lpB = lpC;
        int tn = t + 2; if (tn > Tt - 1) tn = Tt - 1;
        lpC = gp[(size_t)tn * stride] * LOG2E;
        __syncthreads();
    }

    if (s < Ss) afin[s] = a;
    __syncthreads();

    if (tid == 0) {
        int   end = 2 * label_len;
        float al  = afin[end];
        float ap  = (label_len > 0) ? afin[end - 1] : NEGV;
        float M   = fmaxf(al, ap);
        float mn  = fminf(al, ap);
        g_llraw[b] = M + lg2f_(1.0f + ex2f_(mn - M));
    }
}

// ---------------------------------------------------------------------------
// Kernel 3: per-b normalization correction (fp64 cumsum of lse2) + loss
// ---------------------------------------------------------------------------
__global__ void finalize_kernel(const int* __restrict__ act_lens) {
    const int b = blockIdx.x, tid = threadIdx.x;
    const int n = act_lens[b];
    const float* p = g_lse2 + (size_t)b * Tt;
    double sd = 0.0;
    for (int t = tid; t < n; t += 256) sd += (double)p[t];
    __shared__ double red[256];
    red[tid] = sd; __syncthreads();
    for (int o = 128; o > 0; o >>= 1) {
        if (tid < o) red[tid] += red[tid + o];
        __syncthreads();
    }
    if (tid == 0)
        g_losses[b] = (float)((red[0] - (double)g_llraw[b]) * (double)LN2);
}

// ---------------------------------------------------------------------------
// Kernel 4: total = sum(losses) / sum(act_lens)
// ---------------------------------------------------------------------------
__global__ void reduce_kernel(const int* __restrict__ act_lens,
                              float* __restrict__ out)
{
    int lane = threadIdx.x;   // 32 threads; each handles lane and lane+32
    float l = g_losses[lane] + g_losses[lane + 32];
    float n = (float)act_lens[lane] + (float)act_lens[lane + 32];
#pragma unroll
    for (int o = 16; o > 0; o >>= 1) {
        l += __shfl_xor_sync(0xffffffffu, l, o);
        n += __shfl_xor_sync(0xffffffffu, n, o);
    }
    if (lane == 0) out[0] = l / n;
}

extern "C" void kernel_launch(void* const* d_in, const int* in_sizes, int n_in,
                              void* d_out, int out_size)
{
    const float* logits     = (const float*)d_in[0];
    const int*   labels     = (const int*)  d_in[1];
    const int*   act_lens   = (const int*)  d_in[2];
    const int*   label_lens = (const int*)  d_in[3];

    const int rows = Tt * Bb;
    lse_kernel<<<(rows * 32 + 255) / 256, 256>>>(logits);
    ctc_alpha_kernel<<<Bb, 416>>>(logits, labels, act_lens, label_lens);
    finalize_kernel<<<Bb, 256>>>(act_lens);
    reduce_kernel<<<1, 32>>>(act_lens, (float*)d_out);
}

// round 3
// speedup vs baseline: 1.3054x; 1.0008x over previous
#include <cuda_runtime.h>

// Fixed problem shapes
#define Tt 2000
#define Bb 64
#define Vv 163
#define Lmax 200
#define Ss 401              // 2*Lmax + 1
#define THR 224             // 7 warps; thread k owns states 2k, 2k+1
#define NWRP 7
#define NEGV (-1e30f)
#define LOG2E 1.4426950408889634f
#define LN2 0.6931471805599453f

// Static device scratch
__device__ float g_lse2[Bb * Tt];   // transposed [b][t]
__device__ float g_llraw[Bb];
__device__ float g_losses[Bb];

__device__ __forceinline__ float ex2f_(float x) {
    float y; asm("ex2.approx.f32 %0, %1;" : "=f"(y) : "f"(x)); return y;
}
__device__ __forceinline__ float lg2f_(float x) {
    float y; asm("lg2.approx.f32 %0, %1;" : "=f"(y) : "f"(x)); return y;
}

// ---------------------------------------------------------------------------
// Kernel 1: per-(t,b) log2-sum-exp2 over vocab. One warp per row.
// ---------------------------------------------------------------------------
__global__ void lse_kernel(const float* __restrict__ logits) {
    int w = (blockIdx.x * blockDim.x + threadIdx.x) >> 5;
    int lane = threadIdx.x & 31;
    if (w >= Tt * Bb) return;
    const float* row = logits + (size_t)w * Vv;
    float y[6];
    float m = NEGV;
#pragma unroll
    for (int i = 0; i < 6; i++) {
        int v = lane + 32 * i;
        y[i] = (v < Vv) ? row[v] * LOG2E : NEGV;
        m = fmaxf(m, y[i]);
    }
#pragma unroll
    for (int o = 16; o > 0; o >>= 1) m = fmaxf(m, __shfl_xor_sync(0xffffffffu, m, o));
    float sv = 0.f;
#pragma unroll
    for (int i = 0; i < 6; i++) sv += ex2f_(y[i] - m);
#pragma unroll
    for (int o = 16; o > 0; o >>= 1) sv += __shfl_xor_sync(0xffffffffu, sv, o);
    if (lane == 0) {
        int t = w / Bb, b = w % Bb;
        g_lse2[b * Tt + t] = m + lg2f_(sv);
    }
}

// ---------------------------------------------------------------------------
// Kernel 2: CTC forward recursion on RAW log2-logits (normalization folded
// out via shift-invariance; corrected in finalize).
// One CTA per utterance. Thread k owns states (2k, 2k+1) in registers.
// Even (blank) state: 2-way logaddexp; odd (label) state: 3-way.
// Rows staged coalesced into double-buffered smem; gather via LDS.
// One shfl_up + 1 boundary float/warp per step; one barrier per step.
// ---------------------------------------------------------------------------
__global__ void __launch_bounds__(THR, 1) ctc_alpha_kernel(
    const float* __restrict__ logits,
    const int*   __restrict__ labels,
    const int*   __restrict__ act_lens,
    const int*   __restrict__ label_lens)
{
    const int b    = blockIdx.x;
    const int tid  = threadIdx.x;
    const int lane = tid & 31;
    const int w    = tid >> 5;

    __shared__ float rowbuf[2][Vv];     // staged log2-logit rows
    __shared__ float bnd[2][NWRP];      // lane31 aO per warp, double-buffered
    __shared__ float afin[Ss + 1];

    const int act_len   = act_lens[b];
    const int label_len = label_lens[b];
    const int k = tid;                   // state-pair index

    const int  kcl  = (k < Lmax) ? k : (Lmax - 1);
    const int  lab  = labels[b * Lmax + kcl];
    const bool allow = (k == 0) || (lab != labels[b * Lmax + kcl - 1]);
    const bool validE = (k <= Lmax) && (k <= label_len);   // state 2k
    const bool validO = (k < label_len);                    // state 2k+1

    const float* base  = logits + (size_t)b * Vv;
    const size_t stride = (size_t)Bb * Vv;

    // Stage rows 0 and 1
    if (tid < Vv) {
        rowbuf[0][tid] = base[tid] * LOG2E;
        rowbuf[1][tid] = base[stride + tid] * LOG2E;
    }
    __syncthreads();

    // t = 0 init (only states 0 and 1 live)
    float aE = (k == 0 && validE) ? rowbuf[0][0]   : NEGV;
    float aO = (k == 0 && validO) ? rowbuf[0][lab] : NEGV;
    if (lane == 31) bnd[0][w] = aO;

    // Prefetch registers: rB = row t+1-to-be-staged, rA = row behind it
    float rA = 0.f, rB = 0.f;
    if (tid < Vv) {
        rB = base[2 * stride + tid] * LOG2E;   // row 2
        rA = base[3 * stride + tid] * LOG2E;   // row 3
    }
    __syncthreads();

    for (int t = 1; t < act_len; ++t) {
        const float* rc = rowbuf[t & 1];
        float lpB = rc[0];        // blank log-prob (broadcast)
        float lpL = rc[lab];      // this pair's label log-prob (gather)

        float aOp = __shfl_up_sync(0xffffffffu, aO, 1);
        if (lane == 0) aOp = (w > 0) ? bnd[(t - 1) & 1][w - 1] : NEGV;

        // even state 2k: logaddexp2(aE, alpha[2k-1])
        float Me = fmaxf(aE, aOp), mne = fminf(aE, aOp);
        float newE = Me + lg2f_(1.0f + ex2f_(mne - Me)) + lpB;

        // odd state 2k+1: logaddexp3(aO, aE, allow ? alpha[2k-1] : NEG)
        float s2 = allow ? aOp : NEGV;
        float M1 = fmaxf(aO, aE), m1 = fminf(aO, aE);
        float M2 = fmaxf(M1, s2), m2 = fminf(M1, s2);
        float newO = M2 + lg2f_(1.0f + ex2f_(m1 - M2) + ex2f_(m2 - M2)) + lpL;

        aE = validE ? newE : NEGV;
        aO = validO ? newO : NEGV;
        if (lane == 31) bnd[t & 1][w] = aO;

        // rotate row prefetch: stage row t+1, load row t+3
        if (tid < Vv) {
            rowbuf[(t + 1) & 1][tid] = rB;
            rB = rA;
            int tn = t + 3; if (tn > Tt - 1) tn = Tt - 1;
            rA = base[(size_t)tn * stride + tid] * LOG2E;
        }
        __syncthreads();
    }

    if (k <= Lmax) {
        afin[2 * k] = aE;
        if (k < Lmax) afin[2 * k + 1] = aO;
    }
    __syncthreads();

    if (tid == 0) {
        int   end = 2 * label_len;
        float al  = afin[end];
        float ap  = (label_len > 0) ? afin[end - 1] : NEGV;
        float M   = fmaxf(al, ap);
        float mn  = fminf(al, ap);
        g_llraw[b] = M + lg2f_(1.0f + ex2f_(mn - M));
    }
}

// ---------------------------------------------------------------------------
// Kernel 3: per-b normalization correction (fp64 sum of lse2) + loss
// ---------------------------------------------------------------------------
__global__ void finalize_kernel(const int* __restrict__ act_lens) {
    const int b = blockIdx.x, tid = threadIdx.x;
    const int n = act_lens[b];
    const float* p = g_lse2 + (size_t)b * Tt;
    double sd = 0.0;
    for (int t = tid; t < n; t += 256) sd += (double)p[t];
    __shared__ double red[256];
    red[tid] = sd; __syncthreads();
    for (int o = 128; o > 0; o >>= 1) {
        if (tid < o) red[tid] += red[tid + o];
        __syncthreads();
    }
    if (tid == 0)
        g_losses[b] = (float)((red[0] - (double)g_llraw[b]) * (double)LN2);
}

// ---------------------------------------------------------------------------
// Kernel 4: total = sum(losses) / sum(act_lens)
// ---------------------------------------------------------------------------
__global__ void reduce_kernel(const int* __restrict__ act_lens,
                              float* __restrict__ out)
{
    int lane = threadIdx.x;
    float l = g_losses[lane] + g_losses[lane + 32];
    float n = (float)act_lens[lane] + (float)act_lens[lane + 32];
#pragma unroll
    for (int o = 16; o > 0; o >>= 1) {
        l += __shfl_xor_sync(0xffffffffu, l, o);
        n += __shfl_xor_sync(0xffffffffu, n, o);
    }
    if (lane == 0) out[0] = l / n;
}

extern "C" void kernel_launch(void* const* d_in, const int* in_sizes, int n_in,
                              void* d_out, int out_size)
{
    const float* logits     = (const float*)d_in[0];
    const int*   labels     = (const int*)  d_in[1];
    const int*   act_lens   = (const int*)  d_in[2];
    const int*   label_lens = (const int*)  d_in[3];

    const int rows = Tt * Bb;
    lse_kernel<<<(rows * 32 + 255) / 256, 256>>>(logits);
    ctc_alpha_kernel<<<Bb, THR>>>(logits, labels, act_lens, label_lens);
    finalize_kernel<<<Bb, 256>>>(act_lens);
    reduce_kernel<<<1, 32>>>(act_lens, (float*)d_out);
}

// round 4
// speedup vs baseline: 1.5860x; 1.2150x over previous
#include <cuda_runtime.h>

// Fixed problem shapes
#define Tt 2000
#define Bb 64
#define Vv 163
#define Lmax 200
#define NPair 201           // pairs: pair p = states (2p, 2p+1); S = 401
#define NEGV (-1e30f)
#define LOG2E 1.4426950408889634f
#define LN2 0.6931471805599453f

// Superstep config
#define UU 8                // time steps per superstep (halo width in pairs)
#define NWARP 4
#define OWNW 56             // owned pairs per warp (64 ext - UU halo)
#define NPAD 224            // NWARP * OWNW ext coverage
#define RSTR 164            // padded row stride in smem
#define THR (NWARP * 32)

// Static device scratch
__device__ float g_lse2[Bb * Tt];   // transposed [b][t]
__device__ float g_llraw[Bb];
__device__ float g_losses[Bb];

__device__ __forceinline__ float ex2f_(float x) {
    float y; asm("ex2.approx.f32 %0, %1;" : "=f"(y) : "f"(x)); return y;
}
__device__ __forceinline__ float lg2f_(float x) {
    float y; asm("lg2.approx.f32 %0, %1;" : "=f"(y) : "f"(x)); return y;
}
// 2-way / 3-way log2-add-exp2 (max contributes ex2(0)=1)
__device__ __forceinline__ float lae2_(float a, float b) {
    float M = fmaxf(a, b), m = fminf(a, b);
    return M + lg2f_(1.0f + ex2f_(m - M));
}
__device__ __forceinline__ float lae3_(float a, float b, float c) {
    float M1 = fmaxf(a, b), m1 = fminf(a, b);
    float M2 = fmaxf(M1, c), m2 = fminf(M1, c);
    return M2 + lg2f_(1.0f + ex2f_(m1 - M2) + ex2f_(m2 - M2));
}

// ---------------------------------------------------------------------------
// Kernel 1: per-(t,b) log2-sum-exp2 over vocab. One warp per row.
// ---------------------------------------------------------------------------
__global__ void lse_kernel(const float* __restrict__ logits) {
    int w = (blockIdx.x * blockDim.x + threadIdx.x) >> 5;
    int lane = threadIdx.x & 31;
    if (w >= Tt * Bb) return;
    const float* row = logits + (size_t)w * Vv;
    float y[6];
    float m = NEGV;
#pragma unroll
    for (int i = 0; i < 6; i++) {
        int v = lane + 32 * i;
        y[i] = (v < Vv) ? row[v] * LOG2E : NEGV;
        m = fmaxf(m, y[i]);
    }
#pragma unroll
    for (int o = 16; o > 0; o >>= 1) m = fmaxf(m, __shfl_xor_sync(0xffffffffu, m, o));
    float sv = 0.f;
#pragma unroll
    for (int i = 0; i < 6; i++) sv += ex2f_(y[i] - m);
#pragma unroll
    for (int o = 16; o > 0; o >>= 1) sv += __shfl_xor_sync(0xffffffffu, sv, o);
    if (lane == 0) {
        int t = w / Bb, b = w % Bb;
        g_lse2[b * Tt + t] = m + lg2f_(sv);
    }
}

// ---------------------------------------------------------------------------
// Kernel 2: CTC forward on RAW log2-logits, superstepped with halo.
// One CTA (4 warps) per utterance. Lane owns 2 contiguous pairs; warp owns
// 56 pairs + 8-pair left halo. 8 time steps per __syncthreads.
// ---------------------------------------------------------------------------
__global__ void __launch_bounds__(THR, 1) ctc_alpha_kernel(
    const float* __restrict__ logits,
    const int*   __restrict__ labels,
    const int*   __restrict__ act_lens,
    const int*   __restrict__ label_lens)
{
    const int b    = blockIdx.x;
    const int tid  = threadIdx.x;
    const int lane = tid & 31;
    const int w    = tid >> 5;

    __shared__ float2 snap[2][NPAD];
    __shared__ float  rbuf[2][UU * RSTR];

    const int act_len   = act_lens[b];
    const int label_len = label_lens[b];

    // ext pair indices for this lane
    const int base_ext = OWNW * w - UU;
    const int e0 = base_ext + 2 * lane;
    const int e1 = e0 + 1;
    const bool owner = (lane >= UU / 2);       // lanes 4..31 own their pairs

    // labels / allow / validity per pair (clamped safe reads)
    const int p0c = min(max(e0, 0), Lmax - 1);
    const int p1c = min(max(e1, 0), Lmax - 1);
    const int lab0 = labels[b * Lmax + p0c];
    const int lab1 = labels[b * Lmax + p1c];
    const bool allow0 = (e0 > 0) && (lab0 != labels[b * Lmax + max(p0c - 1, 0)]);
    const bool allow1 = (lab1 != lab0);        // e1 >= 1 always has left pair
    const bool vE0 = (e0 >= 0) && (e0 <= label_len) && (e0 <= Lmax);
    const bool vO0 = (e0 >= 0) && (e0 <  label_len);
    const bool vE1 = (e1 >= 0) && (e1 <= label_len) && (e1 <= Lmax);
    const bool vO1 = (e1 >= 0) && (e1 <  label_len);

    const float* base = logits + (size_t)b * Vv;
    const size_t gstr = (size_t)Bb * Vv;

    // --- init snapshots to NEGV ---
    for (int i = tid; i < NPAD; i += THR) {
        snap[0][i] = make_float2(NEGV, NEGV);
        snap[1][i] = make_float2(NEGV, NEGV);
    }
    // --- stage rows t=1..UU into rbuf[0] ---
    {
        int u = tid / Vv, v = tid - u * Vv;
        for (int idx = tid; idx < UU * Vv; idx += THR) {
            int tr = 1 + u; if (tr > Tt - 1) tr = Tt - 1;
            rbuf[0][u * RSTR + v] = base[(size_t)tr * gstr + v] * LOG2E;
            v += THR; if (v >= Vv) { v -= Vv; u++; }
        }
    }
    __syncthreads();
    // --- t=0 init: pair 0 gets row0 values ---
    if (owner) {
        float2 z = make_float2(NEGV, NEGV);
        if (e0 == 0) {
            z.x = base[0] * LOG2E;                       // state 0 (blank)
            z.y = (label_len > 0) ? base[lab0] * LOG2E : NEGV;  // state 1
        }
        snap[0][e0] = (e0 == 0) ? z : make_float2(NEGV, NEGV);
        snap[0][e1] = make_float2(NEGV, NEGV);
    }
    __syncthreads();

    int cur = 0;
    for (int t0 = 1; t0 < act_len; t0 += UU) {
        const float* rb = rbuf[cur];

        // load ext-pair states from snapshot
        float2 P0 = (e0 >= 0) ? snap[cur][e0] : make_float2(NEGV, NEGV);
        float2 P1 = (e1 >= 0) ? snap[cur][e1] : make_float2(NEGV, NEGV);
        float aE0 = P0.x, aO0 = P0.y, aE1 = P1.x, aO1 = P1.y;

        // prefetch all log-probs for this superstep into registers
        float lpB[UU], lpL0[UU], lpL1[UU];
#pragma unroll
        for (int u = 0; u < UU; u++) {
            lpB[u]  = rb[u * RSTR];
            lpL0[u] = rb[u * RSTR + lab0];
            lpL1[u] = rb[u * RSTR + lab1];
        }

        // issue next-superstep row loads (consumed after the step loop)
        float stg[11];
        {
            int u = tid / Vv, v = tid - u * Vv;
#pragma unroll
            for (int i = 0; i < 11; i++) {
                int idx = tid + i * THR;
                if (idx < UU * Vv) {
                    int tr = t0 + UU + u; if (tr > Tt - 1) tr = Tt - 1;
                    stg[i] = base[(size_t)tr * gstr + v];
                    v += THR; if (v >= Vv) { v -= Vv; u++; }
                }
            }
        }

        // 8 time steps, warp-local
#pragma unroll
        for (int u = 0; u < UU; u++) {
            const bool live = (t0 + u) < act_len;
            float aOp = __shfl_up_sync(0xffffffffu, aO1, 1);
            if (lane == 0) aOp = NEGV;
            const float aO0old = aO0;

            // pair e0
            float nE0 = lae2_(aE0, aOp) + lpB[u];
            float nO0 = lae3_(aO0, aE0, allow0 ? aOp : NEGV) + lpL0[u];
            // pair e1 (uses previous-step aO0)
            float nE1 = lae2_(aE1, aO0old) + lpB[u];
            float nO1 = lae3_(aO1, aE1, allow1 ? aO0old : NEGV) + lpL1[u];

            if (live) {
                aE0 = vE0 ? nE0 : NEGV;  aO0 = vO0 ? nO0 : NEGV;
                aE1 = vE1 ? nE1 : NEGV;  aO1 = vO1 ? nO1 : NEGV;
            }
        }

        // write owned pairs to the other snapshot
        if (owner) {
            snap[cur ^ 1][e0] = make_float2(aE0, aO0);
            snap[cur ^ 1][e1] = make_float2(aE1, aO1);
        }
        // store staged rows
        {
            int u = tid / Vv, v = tid - u * Vv;
#pragma unroll
            for (int i = 0; i < 11; i++) {
                int idx = tid + i * THR;
                if (idx < UU * Vv) {
                    rbuf[cur ^ 1][u * RSTR + v] = stg[i] * LOG2E;
                    v += THR; if (v >= Vv) { v -= Vv; u++; }
                }
            }
        }
        __syncthreads();
        cur ^= 1;
    }

    if (tid == 0) {
        float al = snap[cur][label_len].x;                         // state 2L
        float ap = (label_len > 0) ? snap[cur][label_len - 1].y    // state 2L-1
                                   : NEGV;
        g_llraw[b] = lae2_(al, ap);
    }
}

// ---------------------------------------------------------------------------
// Kernel 3: per-b normalization correction (fp64 sum of lse2) + loss
// ---------------------------------------------------------------------------
__global__ void finalize_kernel(const int* __restrict__ act_lens) {
    const int b = blockIdx.x, tid = threadIdx.x;
    const int n = act_lens[b];
    const float* p = g_lse2 + (size_t)b * Tt;
    double sd = 0.0;
    for (int t = tid; t < n; t += 256) sd += (double)p[t];
    __shared__ double red[256];
    red[tid] = sd; __syncthreads();
    for (int o = 128; o > 0; o >>= 1) {
        if (tid < o) red[tid] += red[tid + o];
        __syncthreads();
    }
    if (tid == 0)
        g_losses[b] = (float)((red[0] - (double)g_llraw[b]) * (double)LN2);
}

// ---------------------------------------------------------------------------
// Kernel 4: total = sum(losses) / sum(act_lens)
// ---------------------------------------------------------------------------
__global__ void reduce_kernel(const int* __restrict__ act_lens,
                              float* __restrict__ out)
{
    int lane = threadIdx.x;
    float l = g_losses[lane] + g_losses[lane + 32];
    float n = (float)act_lens[lane] + (float)act_lens[lane + 32];
#pragma unroll
    for (int o = 16; o > 0; o >>= 1) {
        l += __shfl_xor_sync(0xffffffffu, l, o);
        n += __shfl_xor_sync(0xffffffffu, n, o);
    }
    if (lane == 0) out[0] = l / n;
}

extern "C" void kernel_launch(void* const* d_in, const int* in_sizes, int n_in,
                              void* d_out, int out_size)
{
    const float* logits     = (const float*)d_in[0];
    const int*   labels     = (const int*)  d_in[1];
    const int*   act_lens   = (const int*)  d_in[2];
    const int*   label_lens = (const int*)  d_in[3];

    const int rows = Tt * Bb;
    lse_kernel<<<(rows * 32 + 255) / 256, 256>>>(logits);
    ctc_alpha_kernel<<<Bb, THR>>>(logits, labels, act_lens, label_lens);
    finalize_kernel<<<Bb, 256>>>(act_lens);
    reduce_kernel<<<1, 32>>>(act_lens, (float*)d_out);
}

// round 7
// speedup vs baseline: 1.8617x; 1.1738x over previous
#include <cuda_runtime.h>

// Fixed problem shapes
#define Tt 2000
#define Bb 64
#define Vv 163
#define Lmax 200
#define NPair 201
#define NEGV (-1e30f)
#define LOG2E 1.4426950408889634f
#define LN2 0.6931471805599453f

// Superstep config: 8 warps, 1 pair per lane, 6-pair halo = 6 steps/barrier
#define UU 6
#define NWARP 8
#define OWNW 26              // owned pairs per warp (32 - HALO)
#define HALO 6
#define NSNAP 224            // >= NWARP*OWNW = 208
#define RSTR 164             // padded row stride (floats)
#define THR (NWARP * 32)     // 256
#define NSTG 4               // ceil(UU*Vv / THR) = ceil(978/256)

// Static device scratch
__device__ float g_lse2[Bb * Tt];   // transposed [b][t]
__device__ float g_llraw[Bb];
__device__ float g_losses[Bb];

__device__ __forceinline__ float ex2f_(float x) {
    float y; asm("ex2.approx.f32 %0, %1;" : "=f"(y) : "f"(x)); return y;
}
__device__ __forceinline__ float lg2f_(float x) {
    float y; asm("lg2.approx.f32 %0, %1;" : "=f"(y) : "f"(x)); return y;
}
// log2(2^a + 2^b), 2 MUFU
__device__ __forceinline__ float lae2_(float a, float b) {
    float M = fmaxf(a, b), m = fminf(a, b);
    return M + lg2f_(1.0f + ex2f_(m - M));
}

// ---------------------------------------------------------------------------
// Kernel 1: per-(t,b) log2-sum-exp2 over vocab. One warp per row.
// ---------------------------------------------------------------------------
__global__ void lse_kernel(const float* __restrict__ logits) {
    int w = (blockIdx.x * blockDim.x + threadIdx.x) >> 5;
    int lane = threadIdx.x & 31;
    if (w >= Tt * Bb) return;
    const float* row = logits + (size_t)w * Vv;
    float y[6];
    float m = NEGV;
#pragma unroll
    for (int i = 0; i < 6; i++) {
        int v = lane + 32 * i;
        y[i] = (v < Vv) ? row[v] * LOG2E : NEGV;
        m = fmaxf(m, y[i]);
    }
#pragma unroll
    for (int o = 16; o > 0; o >>= 1) m = fmaxf(m, __shfl_xor_sync(0xffffffffu, m, o));
    float sv = 0.f;
#pragma unroll
    for (int i = 0; i < 6; i++) sv += ex2f_(y[i] - m);
#pragma unroll
    for (int o = 16; o > 0; o >>= 1) sv += __shfl_xor_sync(0xffffffffu, sv, o);
    if (lane == 0) {
        int t = w / Bb, b = w % Bb;
        g_lse2[b * Tt + t] = m + lg2f_(sv);
    }
}

// ---------------------------------------------------------------------------
// Kernel 2: CTC forward on RAW log2-logits (softmax normalization folded out;
// corrected in finalize). One CTA (8 warps) per utterance; lane owns ONE
// state pair (blank 2p, label 2p+1); 6-pair left halo per warp; 6 time steps
// per __syncthreads. Shared-subexpression lae3: 4 MUFU per lane-step.
// ---------------------------------------------------------------------------
__global__ void __launch_bounds__(THR, 1) ctc_alpha_kernel(
    const float* __restrict__ logits,
    const int*   __restrict__ labels,
    const int*   __restrict__ act_lens,
    const int*   __restrict__ label_lens)
{
    const int b    = blockIdx.x;
    const int tid  = threadIdx.x;
    const int lane = tid & 31;
    const int w    = tid >> 5;

    __shared__ float2 snap[2][NSNAP];
    __shared__ float  rbuf[2][UU * RSTR];   // raw log2-logit rows

    const int act_len   = act_lens[b];
    const int label_len = label_lens[b];

    // this lane's pair index (HALO leftmost lanes are redundant halo)
    const int  p = OWNW * w - HALO + lane;
    const bool owner = (lane >= HALO) && (p < NSNAP);

    const int  pc   = min(max(p, 0), Lmax - 1);
    const int  lab  = labels[b * Lmax + pc];
    const bool allow = (p > 0) && (p <= Lmax - 1) &&
                       (lab != labels[b * Lmax + max(pc - 1, 0)]);
    const bool vE = (p >= 0) && (p <= label_len);
    const bool vO = (p >= 0) && (p <  label_len);

    const float* base = logits + (size_t)b * Vv;
    const size_t gstr = (size_t)Bb * Vv;

    // staging index map (fixed across supersteps)
    int su[NSTG], sv_[NSTG]; bool sa[NSTG];
#pragma unroll
    for (int i = 0; i < NSTG; i++) {
        int idx = tid + i * THR;
        sa[i] = idx < UU * Vv;
        su[i] = idx / Vv;
        sv_[i] = idx - su[i] * Vv;
    }

    // init snapshots
    for (int i = tid; i < NSNAP; i += THR) {
        snap[0][i] = make_float2(NEGV, NEGV);
        snap[1][i] = make_float2(NEGV, NEGV);
    }
    // stage rows t = 1..UU into rbuf[0]
#pragma unroll
    for (int i = 0; i < NSTG; i++) {
        if (sa[i]) {
            int tr = 1 + su[i]; if (tr > Tt - 1) tr = Tt - 1;
            rbuf[0][su[i] * RSTR + sv_[i]] = base[(size_t)tr * gstr + sv_[i]] * LOG2E;
        }
    }
    __syncthreads();
    // t=0 init: only pair 0 (owned by warp 0, lane HALO)
    if (p == 0 && owner) {
        float aE0 = base[0] * LOG2E;
        float aO0 = (label_len > 0) ? base[lab] * LOG2E : NEGV;
        snap[0][0] = make_float2(aE0, aO0);
    }
    __syncthreads();

    int cur = 0;
    for (int t0 = 1; t0 < act_len; t0 += UU) {
        // load ext pair state
        float2 P = (p >= 0) ? snap[cur][p] : make_float2(NEGV, NEGV);
        float aE = P.x, aO = P.y;

        // preload this superstep's log-probs into registers
        const float* rb = rbuf[cur];
        float lpB[UU], lpL[UU];
#pragma unroll
        for (int u = 0; u < UU; u++) {
            lpB[u] = rb[u * RSTR];          // broadcast
            lpL[u] = rb[u * RSTR + lab];    // gather
        }

        // prefetch next superstep's rows (LDG now, STS after the step loop)
        float g[NSTG];
#pragma unroll
        for (int i = 0; i < NSTG; i++) {
            if (sa[i]) {
                int tr = t0 + UU + su[i]; if (tr > Tt - 1) tr = Tt - 1;
                g[i] = base[(size_t)tr * gstr + sv_[i]];
            }
        }

        // 6 time steps, register/shfl only; 4 MUFU per step
#pragma unroll
        for (int u = 0; u < UU; u++) {
            const bool live = (t0 + u) < act_len;
            float aOp = __shfl_up_sync(0xffffffffu, aO, 1);
            if (lane == 0) aOp = NEGV;

            float q  = lae2_(aE, aOp);                 // log2(2^aE + 2^aOp)
            float r  = allow ? q : aE;
            float nE = q + lpB[u];
            float nO = lae2_(aO, r) + lpL[u];          // lae3 via reuse of q

            if (live) {
                aE = vE ? nE : NEGV;
                aO = vO ? nO : NEGV;
            }
        }

        if (owner) snap[cur ^ 1][p] = make_float2(aE, aO);

        // store staged rows for next superstep
#pragma unroll
        for (int i = 0; i < NSTG; i++) {
            if (sa[i]) rbuf[cur ^ 1][su[i] * RSTR + sv_[i]] = g[i] * LOG2E;
        }
        __syncthreads();
        cur ^= 1;
    }

    if (tid == 0) {
        float al = snap[cur][label_len].x;                        // state 2L
        float ap = (label_len > 0) ? snap[cur][label_len - 1].y   // state 2L-1
                                   : NEGV;
        g_llraw[b] = lae2_(al, ap);
    }
}

// ---------------------------------------------------------------------------
// Kernel 3: per-b normalization correction (fp64 sum of lse2) + loss
// ---------------------------------------------------------------------------
__global__ void finalize_kernel(const int* __restrict__ act_lens) {
    const int b = blockIdx.x, tid = threadIdx.x;
    const int n = act_lens[b];
    const float* pr = g_lse2 + (size_t)b * Tt;
    double sd = 0.0;
    for (int t = tid; t < n; t += 256) sd += (double)pr[t];
    __shared__ double red[256];
    red[tid] = sd; __syncthreads();
    for (int o = 128; o > 0; o >>= 1) {
        if (tid < o) red[tid] += red[tid + o];
        __syncthreads();
    }
    if (tid == 0)
        g_losses[b] = (float)((red[0] - (double)g_llraw[b]) * (double)LN2);
}

// ---------------------------------------------------------------------------
// Kernel 4: total = sum(losses) / sum(act_lens)
// ---------------------------------------------------------------------------
__global__ void reduce_kernel(const int* __restrict__ act_lens,
                              float* __restrict__ out)
{
    int lane = threadIdx.x;
    float l = g_losses[lane] + g_losses[lane + 32];
    float n = (float)act_lens[lane] + (float)act_lens[lane + 32];
#pragma unroll
    for (int o = 16; o > 0; o >>= 1) {
        l += __shfl_xor_sync(0xffffffffu, l, o);
        n += __shfl_xor_sync(0xffffffffu, n, o);
    }
    if (lane == 0) out[0] = l / n;
}

extern "C" void kernel_launch(void* const* d_in, const int* in_sizes, int n_in,
                              void* d_out, int out_size)
{
    const float* logits     = (const float*)d_in[0];
    const int*   labels     = (const int*)  d_in[1];
    const int*   act_lens   = (const int*)  d_in[2];
    const int*   label_lens = (const int*)  d_in[3];

    const int rows = Tt * Bb;
    lse_kernel<<<(rows * 32 + 255) / 256, 256>>>(logits);
    ctc_alpha_kernel<<<Bb, THR>>>(logits, labels, act_lens, label_lens);
    finalize_kernel<<<Bb, 256>>>(act_lens);
    reduce_kernel<<<1, 32>>>(act_lens, (float*)d_out);
}